// round 1
// baseline (speedup 1.0000x reference)
#include <cuda_runtime.h>
#include <cuda_bf16.h>

// Problem constants (fixed by the reference)
#define NIN   64
#define NOUT  32
#define KK    9
#define WELEMS (KK * NIN * NOUT)   // 18432 floats = 73728 bytes

#define FULLMASK 0xFFFFFFFFu

// ---------------- packed f32x2 helpers (Blackwell) ----------------
__device__ __forceinline__ unsigned long long pk2(float lo, float hi) {
    unsigned long long r;
    asm("mov.b64 %0, {%1, %2};" : "=l"(r) : "f"(lo), "f"(hi));
    return r;
}
__device__ __forceinline__ void upk2(unsigned long long v, float& lo, float& hi) {
    asm("mov.b64 {%0, %1}, %2;" : "=f"(lo), "=f"(hi) : "l"(v));
}
__device__ __forceinline__ void fma2(unsigned long long& d, unsigned long long a,
                                     unsigned long long b) {
    asm("fma.rn.f32x2 %0, %1, %2, %0;" : "+l"(d) : "l"(a), "l"(b));
}

// ---------------- main compute kernel ----------------
// One warp processes 4 inputs at a time. lane = output channel (NOUT == 32).
// Weights staged in shared memory as [k][c][d], d contiguous -> conflict-free
// 128B LDS per (k,c).
__global__ void __launch_bounds__(256)
deconv_scatter_kernel(const float* __restrict__ in_feats,
                      const float* __restrict__ weight,
                      const int*   __restrict__ out_idx,
                      float*       __restrict__ out,
                      int N)
{
    extern __shared__ float ws[];   // WELEMS floats

    // cooperative weight load (float4 vectorized)
    {
        const float4* wg4 = reinterpret_cast<const float4*>(weight);
        float4* ws4 = reinterpret_cast<float4*>(ws);
        for (int i = threadIdx.x; i < WELEMS / 4; i += blockDim.x)
            ws4[i] = wg4[i];
    }
    __syncthreads();

    const int lane   = threadIdx.x & 31;
    const int warp   = blockIdx.x * (blockDim.x >> 5) + (threadIdx.x >> 5);
    const int nwarps = gridDim.x * (blockDim.x >> 5);

    for (int n0 = warp * 4; n0 < N; n0 += nwarps * 4) {
        const bool full = (n0 + 3) < N;
        const int n1 = full ? n0 + 1 : min(n0 + 1, N - 1);
        const int n2 = full ? n0 + 2 : min(n0 + 2, N - 1);
        const int n3 = full ? n0 + 3 : min(n0 + 3, N - 1);

        // stage the 4 input rows into registers (2 x 32 channels each)
        float r0a = in_feats[(size_t)n0 * NIN + lane];
        float r0b = in_feats[(size_t)n0 * NIN + 32 + lane];
        float r1a = in_feats[(size_t)n1 * NIN + lane];
        float r1b = in_feats[(size_t)n1 * NIN + 32 + lane];
        float r2a = in_feats[(size_t)n2 * NIN + lane];
        float r2b = in_feats[(size_t)n2 * NIN + 32 + lane];
        float r3a = in_feats[(size_t)n3 * NIN + lane];
        float r3b = in_feats[(size_t)n3 * NIN + 32 + lane];

        unsigned long long acc01[KK], acc23[KK];
        #pragma unroll
        for (int k = 0; k < KK; ++k) { acc01[k] = 0ull; acc23[k] = 0ull; }

        // first 32 input channels
        #pragma unroll 4
        for (int c = 0; c < 32; ++c) {
            float a0 = __shfl_sync(FULLMASK, r0a, c);
            float a1 = __shfl_sync(FULLMASK, r1a, c);
            float a2 = __shfl_sync(FULLMASK, r2a, c);
            float a3 = __shfl_sync(FULLMASK, r3a, c);
            unsigned long long A01 = pk2(a0, a1);
            unsigned long long A23 = pk2(a2, a3);
            const float* wc = ws + c * NOUT + lane;
            #pragma unroll
            for (int k = 0; k < KK; ++k) {
                float w = wc[k * (NIN * NOUT)];
                unsigned long long W = pk2(w, w);
                fma2(acc01[k], A01, W);
                fma2(acc23[k], A23, W);
            }
        }
        // last 32 input channels
        #pragma unroll 4
        for (int c = 0; c < 32; ++c) {
            float a0 = __shfl_sync(FULLMASK, r0b, c);
            float a1 = __shfl_sync(FULLMASK, r1b, c);
            float a2 = __shfl_sync(FULLMASK, r2b, c);
            float a3 = __shfl_sync(FULLMASK, r3b, c);
            unsigned long long A01 = pk2(a0, a1);
            unsigned long long A23 = pk2(a2, a3);
            const float* wc = ws + (32 + c) * NOUT + lane;
            #pragma unroll
            for (int k = 0; k < KK; ++k) {
                float w = wc[k * (NIN * NOUT)];
                unsigned long long W = pk2(w, w);
                fma2(acc01[k], A01, W);
                fma2(acc23[k], A23, W);
            }
        }

        // scatter-accumulate: 9 coalesced 128B atomic rows per input
        #pragma unroll
        for (int k = 0; k < KK; ++k) {
            float v0, v1, v2, v3;
            upk2(acc01[k], v0, v1);
            upk2(acc23[k], v2, v3);
            int i0 = out_idx[(size_t)n0 * KK + k];
            atomicAdd(&out[(size_t)i0 * NOUT + lane], v0);
            if (full || n0 + 1 < N) {
                int i1 = out_idx[(size_t)n1 * KK + k];
                atomicAdd(&out[(size_t)i1 * NOUT + lane], v1);
            }
            if (full || n0 + 2 < N) {
                int i2 = out_idx[(size_t)n2 * KK + k];
                atomicAdd(&out[(size_t)i2 * NOUT + lane], v2);
            }
            if (full || n0 + 3 < N) {
                int i3 = out_idx[(size_t)n3 * KK + k];
                atomicAdd(&out[(size_t)i3 * NOUT + lane], v3);
            }
        }
    }
}

// ---------------- bias + ReLU finalize (float4) ----------------
__global__ void finalize_kernel(float* __restrict__ out,
                                const float* __restrict__ bias,
                                int total4)
{
    int i = blockIdx.x * blockDim.x + threadIdx.x;
    if (i >= total4) return;
    float4 v = reinterpret_cast<float4*>(out)[i];
    int d = (i * 4) & (NOUT - 1);
    v.x = fmaxf(v.x + __ldg(&bias[d + 0]), 0.f);
    v.y = fmaxf(v.y + __ldg(&bias[d + 1]), 0.f);
    v.z = fmaxf(v.z + __ldg(&bias[d + 2]), 0.f);
    v.w = fmaxf(v.w + __ldg(&bias[d + 3]), 0.f);
    reinterpret_cast<float4*>(out)[i] = v;
}

extern "C" void kernel_launch(void* const* d_in, const int* in_sizes, int n_in,
                              void* d_out, int out_size)
{
    const float* in_feats = (const float*)d_in[0];
    const float* weight   = (const float*)d_in[1];
    const float* bias     = (const float*)d_in[2];
    const int*   out_idx  = (const int*)d_in[3];
    float* out = (float*)d_out;

    const int N = in_sizes[0] / NIN;

    // zero the (poisoned) output buffer before scatter-adds
    cudaMemsetAsync(out, 0, (size_t)out_size * sizeof(float));

    // 72KB dynamic smem needs opt-in
    const int smem = WELEMS * sizeof(float);
    cudaFuncSetAttribute(deconv_scatter_kernel,
                         cudaFuncAttributeMaxDynamicSharedMemorySize, smem);

    int blocks = 148 * 3;   // ~3 CTAs/SM at 72KB smem, grid-stride over inputs
    int maxBlocks = (N + 31) / 32;
    if (blocks > maxBlocks) blocks = maxBlocks;
    deconv_scatter_kernel<<<blocks, 256, smem>>>(in_feats, weight, out_idx, out, N);

    int total4 = out_size / 4;
    finalize_kernel<<<(total4 + 255) / 256, 256>>>(out, bias, total4);
}

// round 2
// speedup vs baseline: 1.1207x; 1.1207x over previous
#include <cuda_runtime.h>
#include <cuda_bf16.h>

// Problem constants (fixed by the reference)
#define NIN   64
#define NOUT  32
#define KK    9
#define WELEMS (KK * NIN * NOUT)   // 18432 floats = 73728 bytes

#define FULLMASK 0xFFFFFFFFu

// ---------------- packed f32x2 helpers (Blackwell) ----------------
__device__ __forceinline__ unsigned long long pk2(float lo, float hi) {
    unsigned long long r;
    asm("mov.b64 %0, {%1, %2};" : "=l"(r) : "f"(lo), "f"(hi));
    return r;
}
__device__ __forceinline__ void upk2(unsigned long long v, float& lo, float& hi) {
    asm("mov.b64 {%0, %1}, %2;" : "=f"(lo), "=f"(hi) : "l"(v));
}
__device__ __forceinline__ void fma2(unsigned long long& d, unsigned long long a,
                                     unsigned long long b) {
    asm("fma.rn.f32x2 %0, %1, %2, %0;" : "+l"(d) : "l"(a), "l"(b));
}

// No-op kernel purely to align ncu's -s 5 -c 1 window onto the main kernel.
// Kernel order per replay: dummy(0), main(1), finalize(2), dummy(3) ->
// kernel #5 == main of replay 2.
__global__ void dummy_kernel() {}

// ---------------- main compute kernel ----------------
// One warp processes 8 inputs per tile. lane = output channel (NOUT == 32).
// Weights staged once per CTA in shared memory as [k][c][d] (d contiguous ->
// conflict-free 128B LDS broadcast rows). Accumulators are f32x2 pairs over
// the 8-input tile so each fma.rn.f32x2 performs 2 FMAs.
__global__ void __launch_bounds__(256, 2)
deconv_scatter_kernel(const float* __restrict__ in_feats,
                      const float* __restrict__ weight,
                      const int*   __restrict__ out_idx,
                      float*       __restrict__ out,
                      int N)
{
    extern __shared__ float ws[];   // WELEMS floats (72 KB)

    // cooperative weight load (float4 vectorized)
    {
        const float4* wg4 = reinterpret_cast<const float4*>(weight);
        float4* ws4 = reinterpret_cast<float4*>(ws);
        for (int i = threadIdx.x; i < WELEMS / 4; i += blockDim.x)
            ws4[i] = wg4[i];
    }
    __syncthreads();

    const int lane   = threadIdx.x & 31;
    const int gwarp  = blockIdx.x * (blockDim.x >> 5) + (threadIdx.x >> 5);
    const int nwarps = gridDim.x * (blockDim.x >> 5);
    const int ntiles = N >> 3;          // full 8-input tiles

    const float* wl = ws + lane;

    for (int t = gwarp; t < ntiles; t += nwarps) {
        const int base = t << 3;

        // stage 8 input rows: row i = 32 lanes x float2 (channels 2*lane, 2*lane+1)
        const float2* inp = reinterpret_cast<const float2*>(in_feats + (size_t)base * NIN);
        float2 r0 = inp[0 * 32 + lane];
        float2 r1 = inp[1 * 32 + lane];
        float2 r2 = inp[2 * 32 + lane];
        float2 r3 = inp[3 * 32 + lane];
        float2 r4 = inp[4 * 32 + lane];
        float2 r5 = inp[5 * 32 + lane];
        float2 r6 = inp[6 * 32 + lane];
        float2 r7 = inp[7 * 32 + lane];

        unsigned long long a01[KK], a23[KK], a45[KK], a67[KK];
        #pragma unroll
        for (int k = 0; k < KK; ++k) { a01[k]=0ull; a23[k]=0ull; a45[k]=0ull; a67[k]=0ull; }

        #pragma unroll 2
        for (int s = 0; s < 32; ++s) {
            // channel c = 2*s  (x components)
            {
                float b0 = __shfl_sync(FULLMASK, r0.x, s);
                float b1 = __shfl_sync(FULLMASK, r1.x, s);
                float b2 = __shfl_sync(FULLMASK, r2.x, s);
                float b3 = __shfl_sync(FULLMASK, r3.x, s);
                float b4 = __shfl_sync(FULLMASK, r4.x, s);
                float b5 = __shfl_sync(FULLMASK, r5.x, s);
                float b6 = __shfl_sync(FULLMASK, r6.x, s);
                float b7 = __shfl_sync(FULLMASK, r7.x, s);
                unsigned long long A01 = pk2(b0, b1);
                unsigned long long A23 = pk2(b2, b3);
                unsigned long long A45 = pk2(b4, b5);
                unsigned long long A67 = pk2(b6, b7);
                const float* wc = wl + (2 * s) * NOUT;
                #pragma unroll
                for (int k = 0; k < KK; ++k) {
                    float w = wc[k * (NIN * NOUT)];
                    unsigned long long W = pk2(w, w);
                    fma2(a01[k], A01, W);
                    fma2(a23[k], A23, W);
                    fma2(a45[k], A45, W);
                    fma2(a67[k], A67, W);
                }
            }
            // channel c = 2*s + 1  (y components)
            {
                float b0 = __shfl_sync(FULLMASK, r0.y, s);
                float b1 = __shfl_sync(FULLMASK, r1.y, s);
                float b2 = __shfl_sync(FULLMASK, r2.y, s);
                float b3 = __shfl_sync(FULLMASK, r3.y, s);
                float b4 = __shfl_sync(FULLMASK, r4.y, s);
                float b5 = __shfl_sync(FULLMASK, r5.y, s);
                float b6 = __shfl_sync(FULLMASK, r6.y, s);
                float b7 = __shfl_sync(FULLMASK, r7.y, s);
                unsigned long long A01 = pk2(b0, b1);
                unsigned long long A23 = pk2(b2, b3);
                unsigned long long A45 = pk2(b4, b5);
                unsigned long long A67 = pk2(b6, b7);
                const float* wc = wl + (2 * s + 1) * NOUT;
                #pragma unroll
                for (int k = 0; k < KK; ++k) {
                    float w = wc[k * (NIN * NOUT)];
                    unsigned long long W = pk2(w, w);
                    fma2(a01[k], A01, W);
                    fma2(a23[k], A23, W);
                    fma2(a45[k], A45, W);
                    fma2(a67[k], A67, W);
                }
            }
        }

        // scatter-accumulate: 9 coalesced 128B atomic rows per input
        const int* oi = out_idx + (size_t)base * KK;
        #pragma unroll
        for (int k = 0; k < KK; ++k) {
            float v0, v1, v2, v3, v4, v5, v6, v7;
            upk2(a01[k], v0, v1);
            upk2(a23[k], v2, v3);
            upk2(a45[k], v4, v5);
            upk2(a67[k], v6, v7);
            atomicAdd(&out[(size_t)oi[0 * KK + k] * NOUT + lane], v0);
            atomicAdd(&out[(size_t)oi[1 * KK + k] * NOUT + lane], v1);
            atomicAdd(&out[(size_t)oi[2 * KK + k] * NOUT + lane], v2);
            atomicAdd(&out[(size_t)oi[3 * KK + k] * NOUT + lane], v3);
            atomicAdd(&out[(size_t)oi[4 * KK + k] * NOUT + lane], v4);
            atomicAdd(&out[(size_t)oi[5 * KK + k] * NOUT + lane], v5);
            atomicAdd(&out[(size_t)oi[6 * KK + k] * NOUT + lane], v6);
            atomicAdd(&out[(size_t)oi[7 * KK + k] * NOUT + lane], v7);
        }
    }

    // remainder inputs (N % 8) — one input per warp (not hit for N=262144)
    for (int n = (ntiles << 3) + gwarp; n < N; n += nwarps) {
        const float2* inp = reinterpret_cast<const float2*>(in_feats + (size_t)n * NIN);
        float2 r = inp[lane];
        float acc[KK];
        #pragma unroll
        for (int k = 0; k < KK; ++k) acc[k] = 0.f;
        for (int s = 0; s < 32; ++s) {
            float ax = __shfl_sync(FULLMASK, r.x, s);
            float ay = __shfl_sync(FULLMASK, r.y, s);
            const float* wc = ws + (2 * s) * NOUT + lane;
            #pragma unroll
            for (int k = 0; k < KK; ++k) {
                acc[k] = fmaf(ax, wc[k * (NIN * NOUT)], acc[k]);
                acc[k] = fmaf(ay, wc[k * (NIN * NOUT) + NOUT], acc[k]);
            }
        }
        #pragma unroll
        for (int k = 0; k < KK; ++k) {
            int idx = out_idx[(size_t)n * KK + k];
            atomicAdd(&out[(size_t)idx * NOUT + lane], acc[k]);
        }
    }
}

// ---------------- bias + ReLU finalize (float4) ----------------
__global__ void finalize_kernel(float* __restrict__ out,
                                const float* __restrict__ bias,
                                int total4)
{
    int i = blockIdx.x * blockDim.x + threadIdx.x;
    if (i >= total4) return;
    float4 v = reinterpret_cast<float4*>(out)[i];
    int d = (i * 4) & (NOUT - 1);
    v.x = fmaxf(v.x + __ldg(&bias[d + 0]), 0.f);
    v.y = fmaxf(v.y + __ldg(&bias[d + 1]), 0.f);
    v.z = fmaxf(v.z + __ldg(&bias[d + 2]), 0.f);
    v.w = fmaxf(v.w + __ldg(&bias[d + 3]), 0.f);
    reinterpret_cast<float4*>(out)[i] = v;
}

extern "C" void kernel_launch(void* const* d_in, const int* in_sizes, int n_in,
                              void* d_out, int out_size)
{
    const float* in_feats = (const float*)d_in[0];
    const float* weight   = (const float*)d_in[1];
    const float* bias     = (const float*)d_in[2];
    const int*   out_idx  = (const int*)d_in[3];
    float* out = (float*)d_out;

    const int N = in_sizes[0] / NIN;

    // profiling alignment: main kernel lands at kernel index ≡ 1 (mod 4)
    dummy_kernel<<<1, 1>>>();

    // zero the (poisoned) output buffer before scatter-adds
    cudaMemsetAsync(out, 0, (size_t)out_size * sizeof(float));

    // 72KB dynamic smem needs opt-in
    const int smem = WELEMS * sizeof(float);
    cudaFuncSetAttribute(deconv_scatter_kernel,
                         cudaFuncAttributeMaxDynamicSharedMemorySize, smem);

    int blocks = 148 * 2;   // 2 CTAs/SM (72KB smem, 128 regs), grid-stride over tiles
    int maxBlocks = (N + 63) / 64;   // 8 warps * 8 inputs per CTA
    if (blocks > maxBlocks) blocks = maxBlocks;
    deconv_scatter_kernel<<<blocks, 256, smem>>>(in_feats, weight, out_idx, out, N);

    int total4 = out_size / 4;
    finalize_kernel<<<(total4 + 255) / 256, 256>>>(out, bias, total4);

    dummy_kernel<<<1, 1>>>();
}